// round 15
// baseline (speedup 1.0000x reference)
#include <cuda_runtime.h>
#include <cuda_bf16.h>

// Problem constants
#define BB 4096
#define EE 64
#define HH 512
#define TOPK 8

// Precomputed contractions: v_c[68] = Wc @ Ws_c ; v_e[7] = We @ Ws_e ;
// consts[0] = bc·Ws_c ; consts[1] = be·Ws_e + bs
__device__ float g_vc[68];
__device__ float g_ve[7];
__device__ float g_cb[2];

// ---------------------------------------------------------------------------
// Kernel 1: pre-contract weights against Ws. 77 blocks, each reduces 512 elems.
// rows 0..67 -> v_c, 68..74 -> v_e, 75 -> c0, 76 -> e0+bs
// ---------------------------------------------------------------------------
__global__ __launch_bounds__(128) void prep_kernel(
    const float* __restrict__ Wc, const float* __restrict__ bc,
    const float* __restrict__ We, const float* __restrict__ be,
    const float* __restrict__ Ws, const float* __restrict__ bs)
{
    __shared__ float red[128];
    const int row = blockIdx.x;
    const float* src;
    const float* vec;
    if (row < 68)       { src = Wc + row * HH;        vec = Ws + HH; }
    else if (row < 75)  { src = We + (row - 68) * HH; vec = Ws;      }
    else if (row == 75) { src = bc;                   vec = Ws + HH; }
    else                { src = be;                   vec = Ws;      }

    float s = 0.f;
    for (int h = threadIdx.x; h < HH; h += 128)
        s += src[h] * vec[h];
    red[threadIdx.x] = s;
    __syncthreads();
    #pragma unroll
    for (int off = 64; off > 0; off >>= 1) {
        if (threadIdx.x < off) red[threadIdx.x] += red[threadIdx.x + off];
        __syncthreads();
    }
    if (threadIdx.x == 0) {
        float r = red[0];
        if (row < 68)       g_vc[row] = r;
        else if (row < 75)  g_ve[row - 68] = r;
        else if (row == 75) g_cb[0] = r;
        else                g_cb[1] = r + bs[0];
    }
}

// ---------------------------------------------------------------------------
// Kernel 2: one warp per batch row. Lane l owns experts 2l and 2l+1.
// ---------------------------------------------------------------------------
__global__ __launch_bounds__(256) void router_kernel(
    const float* __restrict__ x_context,   // [B,68]
    const float* __restrict__ x_q,         // [B,E,3]
    const float* __restrict__ x_reward,    // [B,E,2]
    const float* __restrict__ x_risk,      // [B,E,2]
    float* __restrict__ out_action,        // [B,3]
    float* __restrict__ out_gate,          // [B,E]
    float* __restrict__ out_logits)        // [B,E]
{
    const int lane = threadIdx.x & 31;
    const int warp = threadIdx.x >> 5;
    const int b = blockIdx.x * 8 + warp;

    // ---- context score: dot68(x_context[b], v_c) ----
    const float* xcb = x_context + (long)b * 68;
    float t = xcb[lane] * g_vc[lane] + xcb[lane + 32] * g_vc[lane + 32];
    if (lane < 4) t += xcb[lane + 64] * g_vc[lane + 64];
    #pragma unroll
    for (int o = 16; o > 0; o >>= 1) t += __shfl_xor_sync(0xFFFFFFFFu, t, o);
    const float rowbias = t + g_cb[0] + g_cb[1];   // ctx_score + (be·Ws_e + bs)

    // ---- per-expert logits (2 experts per lane) ----
    const float ve0 = g_ve[0], ve1 = g_ve[1], ve2 = g_ve[2],
                ve3 = g_ve[3], ve4 = g_ve[4], ve5 = g_ve[5], ve6 = g_ve[6];

    const int e0 = 2 * lane;
    const float* q = x_q + (long)b * (EE * 3) + e0 * 3;          // 6 contiguous floats
    const float q00 = q[0], q01 = q[1], q02 = q[2];
    const float q10 = q[3], q11 = q[4], q12 = q[5];
    const float4 rr = *(const float4*)(x_reward + (long)b * (EE * 2) + e0 * 2);
    const float4 kk = *(const float4*)(x_risk   + (long)b * (EE * 2) + e0 * 2);

    const float l0 = ve0*q00 + ve1*q01 + ve2*q02 + ve3*rr.x + ve4*rr.y
                   + ve5*kk.x + ve6*kk.y + rowbias;
    const float l1 = ve0*q10 + ve1*q11 + ve2*q12 + ve3*rr.z + ve4*rr.w
                   + ve5*kk.z + ve6*kk.w + rowbias;

    // ---- rank counting (matches lax.top_k: ties broken toward lower index) ----
    int r0 = 0, r1 = 0;
    #pragma unroll
    for (int s = 0; s < 32; s++) {
        const float a = __shfl_sync(0xFFFFFFFFu, l0, s);
        const float c = __shfl_sync(0xFFFFFFFFu, l1, s);
        const int ja = 2 * s, jb = 2 * s + 1;
        r0 += (a > l0) | ((a == l0) & (ja < e0));
        r0 += (c > l0) | ((c == l0) & (jb < e0));
        r1 += (a > l1) | ((a == l1) & (ja < e0 + 1));
        r1 += (c > l1) | ((c == l1) & (jb < e0 + 1));
    }

    // ---- softmax over top-8 (others exactly 0, matching NEG_INF underflow) ----
    float m = fmaxf(l0, l1);
    #pragma unroll
    for (int o = 16; o > 0; o >>= 1)
        m = fmaxf(m, __shfl_xor_sync(0xFFFFFFFFu, m, o));

    const float s0 = (r0 < TOPK) ? expf(l0 - m) : 0.f;
    const float s1 = (r1 < TOPK) ? expf(l1 - m) : 0.f;
    float ssum = s0 + s1;
    #pragma unroll
    for (int o = 16; o > 0; o >>= 1)
        ssum += __shfl_xor_sync(0xFFFFFFFFu, ssum, o);
    const float inv = 1.f / ssum;
    const float g0 = s0 * inv, g1 = s1 * inv;

    // ---- outputs ----
    ((float2*)(out_gate   + (long)b * EE))[lane] = make_float2(g0, g1);
    ((float2*)(out_logits + (long)b * EE))[lane] = make_float2(l0, l1);

    float a0 = g0 * q00 + g1 * q10;
    float a1 = g0 * q01 + g1 * q11;
    float a2 = g0 * q02 + g1 * q12;
    #pragma unroll
    for (int o = 16; o > 0; o >>= 1) {
        a0 += __shfl_xor_sync(0xFFFFFFFFu, a0, o);
        a1 += __shfl_xor_sync(0xFFFFFFFFu, a1, o);
        a2 += __shfl_xor_sync(0xFFFFFFFFu, a2, o);
    }
    if (lane == 0) {
        float* oa = out_action + (long)b * 3;
        oa[0] = a0; oa[1] = a1; oa[2] = a2;
    }
}

extern "C" void kernel_launch(void* const* d_in, const int* in_sizes, int n_in,
                              void* d_out, int out_size)
{
    // metadata order: x_context, x_q_values, x_reward, x_risk, Wc, bc, We, be, Ws, bs
    const float* x_context = (const float*)d_in[0];
    const float* x_q       = (const float*)d_in[1];
    const float* x_reward  = (const float*)d_in[2];
    const float* x_risk    = (const float*)d_in[3];
    const float* Wc        = (const float*)d_in[4];
    const float* bc        = (const float*)d_in[5];
    const float* We        = (const float*)d_in[6];
    const float* be        = (const float*)d_in[7];
    const float* Ws        = (const float*)d_in[8];
    const float* bs        = (const float*)d_in[9];

    float* out        = (float*)d_out;
    float* out_action = out;                       // [B,3]
    float* out_gate   = out + (long)BB * 3;        // [B,E]
    float* out_logits = out + (long)BB * 3 + (long)BB * EE;  // [B,E]

    prep_kernel<<<77, 128>>>(Wc, bc, We, be, Ws, bs);
    router_kernel<<<BB / 8, 256>>>(x_context, x_q, x_reward, x_risk,
                                   out_action, out_gate, out_logits);
}

// round 16
// speedup vs baseline: 1.2149x; 1.2149x over previous
#include <cuda_runtime.h>
#include <cuda_bf16.h>

// Problem constants
#define BB 4096
#define EE 64
#define HH 512
#define TOPK 8

// Precomputed contractions: v_c[68] = Wc @ Ws_c ; v_e[7] = We @ Ws_e ;
// consts[0] = bc·Ws_c ; consts[1] = be·Ws_e + bs
__device__ float g_vc[68];
__device__ float g_ve[7];
__device__ float g_cb[2];

// ---------------------------------------------------------------------------
// Kernel 1: pre-contract weights against Ws. 77 blocks, each reduces 512 elems.
// rows 0..67 -> v_c, 68..74 -> v_e, 75 -> c0, 76 -> e0+bs
// ---------------------------------------------------------------------------
__global__ __launch_bounds__(128) void prep_kernel(
    const float* __restrict__ Wc, const float* __restrict__ bc,
    const float* __restrict__ We, const float* __restrict__ be,
    const float* __restrict__ Ws, const float* __restrict__ bs)
{
    __shared__ float red[4];
    const int row = blockIdx.x;
    const int lane = threadIdx.x & 31;
    const int warp = threadIdx.x >> 5;
    const float* src;
    const float* vec;
    if (row < 68)       { src = Wc + row * HH;        vec = Ws + HH; }
    else if (row < 75)  { src = We + (row - 68) * HH; vec = Ws;      }
    else if (row == 75) { src = bc;                   vec = Ws + HH; }
    else                { src = be;                   vec = Ws;      }

    float s = 0.f;
    #pragma unroll
    for (int h = threadIdx.x; h < HH; h += 128)
        s += src[h] * vec[h];
    #pragma unroll
    for (int o = 16; o > 0; o >>= 1) s += __shfl_xor_sync(0xFFFFFFFFu, s, o);
    if (lane == 0) red[warp] = s;
    __syncthreads();
    if (threadIdx.x == 0) {
        float r = red[0] + red[1] + red[2] + red[3];
        if (row < 68)       g_vc[row] = r;
        else if (row < 75)  g_ve[row - 68] = r;
        else if (row == 75) g_cb[0] = r;
        else                g_cb[1] = r + bs[0];
    }
}

// ---------------------------------------------------------------------------
// Kernel 2: one warp per batch row. Lane l owns experts 2l and 2l+1.
// ---------------------------------------------------------------------------
__global__ __launch_bounds__(256) void router_kernel(
    const float* __restrict__ x_context,   // [B,68]
    const float* __restrict__ x_q,         // [B,E,3]
    const float* __restrict__ x_reward,    // [B,E,2]
    const float* __restrict__ x_risk,      // [B,E,2]
    float* __restrict__ out_action,        // [B,3]
    float* __restrict__ out_gate,          // [B,E]
    float* __restrict__ out_logits)        // [B,E]
{
    const int lane = threadIdx.x & 31;
    const int warp = threadIdx.x >> 5;
    const int b = blockIdx.x * 8 + warp;

    // ---- context score: dot68(x_context[b], v_c) ----
    const float* xcb = x_context + (long)b * 68;
    float t = xcb[lane] * g_vc[lane] + xcb[lane + 32] * g_vc[lane + 32];
    if (lane < 4) t += xcb[lane + 64] * g_vc[lane + 64];
    #pragma unroll
    for (int o = 16; o > 0; o >>= 1) t += __shfl_xor_sync(0xFFFFFFFFu, t, o);
    const float rowbias = t + g_cb[0] + g_cb[1];   // ctx_score + (be·Ws_e + bs)

    // ---- per-expert logits (2 experts per lane) ----
    const float ve0 = g_ve[0], ve1 = g_ve[1], ve2 = g_ve[2],
                ve3 = g_ve[3], ve4 = g_ve[4], ve5 = g_ve[5], ve6 = g_ve[6];

    const int e0 = 2 * lane;
    // 6 floats at offset e0*3 (always even) -> three aligned 8-byte loads
    const float2* q2 = (const float2*)(x_q + (long)b * (EE * 3)) + 3 * lane;
    const float2 qa = q2[0], qb = q2[1], qc = q2[2];
    const float q00 = qa.x, q01 = qa.y, q02 = qb.x;
    const float q10 = qb.y, q11 = qc.x, q12 = qc.y;
    const float4 rr = *(const float4*)(x_reward + (long)b * (EE * 2) + e0 * 2);
    const float4 kk = *(const float4*)(x_risk   + (long)b * (EE * 2) + e0 * 2);

    const float l0 = ve0*q00 + ve1*q01 + ve2*q02 + ve3*rr.x + ve4*rr.y
                   + ve5*kk.x + ve6*kk.y + rowbias;
    const float l1 = ve0*q10 + ve1*q11 + ve2*q12 + ve3*rr.z + ve4*rr.w
                   + ve5*kk.z + ve6*kk.w + rowbias;

    // ---- strict-greater rank counting ----
    // Ties at equal fp32 logits only change the selection set if they straddle
    // the rank-8 boundary exactly; both tied values otherwise receive the same
    // rank and land on the same side, matching lax.top_k's selection.
    int r0 = 0, r1 = 0;
    #pragma unroll
    for (int s = 0; s < 32; s++) {
        const float a = __shfl_sync(0xFFFFFFFFu, l0, s);
        const float c = __shfl_sync(0xFFFFFFFFu, l1, s);
        r0 += (a > l0); r0 += (c > l0);
        r1 += (a > l1); r1 += (c > l1);
    }

    // ---- softmax over top-8 (others exactly 0, matching NEG_INF underflow) ----
    float m = fmaxf(l0, l1);
    #pragma unroll
    for (int o = 16; o > 0; o >>= 1)
        m = fmaxf(m, __shfl_xor_sync(0xFFFFFFFFu, m, o));

    const float s0 = (r0 < TOPK) ? __expf(l0 - m) : 0.f;
    const float s1 = (r1 < TOPK) ? __expf(l1 - m) : 0.f;
    float ssum = s0 + s1;
    #pragma unroll
    for (int o = 16; o > 0; o >>= 1)
        ssum += __shfl_xor_sync(0xFFFFFFFFu, ssum, o);
    const float inv = 1.f / ssum;
    const float g0 = s0 * inv, g1 = s1 * inv;

    // ---- outputs ----
    ((float2*)(out_gate   + (long)b * EE))[lane] = make_float2(g0, g1);
    ((float2*)(out_logits + (long)b * EE))[lane] = make_float2(l0, l1);

    float a0 = g0 * q00 + g1 * q10;
    float a1 = g0 * q01 + g1 * q11;
    float a2 = g0 * q02 + g1 * q12;
    #pragma unroll
    for (int o = 16; o > 0; o >>= 1) {
        a0 += __shfl_xor_sync(0xFFFFFFFFu, a0, o);
        a1 += __shfl_xor_sync(0xFFFFFFFFu, a1, o);
        a2 += __shfl_xor_sync(0xFFFFFFFFu, a2, o);
    }
    if (lane == 0) {
        float* oa = out_action + (long)b * 3;
        oa[0] = a0; oa[1] = a1; oa[2] = a2;
    }
}

extern "C" void kernel_launch(void* const* d_in, const int* in_sizes, int n_in,
                              void* d_out, int out_size)
{
    // metadata order: x_context, x_q_values, x_reward, x_risk, Wc, bc, We, be, Ws, bs
    const float* x_context = (const float*)d_in[0];
    const float* x_q       = (const float*)d_in[1];
    const float* x_reward  = (const float*)d_in[2];
    const float* x_risk    = (const float*)d_in[3];
    const float* Wc        = (const float*)d_in[4];
    const float* bc        = (const float*)d_in[5];
    const float* We        = (const float*)d_in[6];
    const float* be        = (const float*)d_in[7];
    const float* Ws        = (const float*)d_in[8];
    const float* bs        = (const float*)d_in[9];

    float* out        = (float*)d_out;
    float* out_action = out;                       // [B,3]
    float* out_gate   = out + (long)BB * 3;        // [B,E]
    float* out_logits = out + (long)BB * 3 + (long)BB * EE;  // [B,E]

    prep_kernel<<<77, 128>>>(Wc, bc, We, be, Ws, bs);
    router_kernel<<<BB / 8, 256>>>(x_context, x_q, x_reward, x_risk,
                                   out_action, out_gate, out_logits);
}